// round 1
// baseline (speedup 1.0000x reference)
#include <cuda_runtime.h>
#include <math.h>

#define BB 16
#define CC 32
#define NN 265
#define HW (NN*NN)          // 70225
#define KK 13               // width modes
#define SS 25               // height modes (s = si-12)
#define LL 4
#define BCHW (BB*CC*HW)     // 35,955,200

// ---------------- device scratch (statics; no allocation allowed) ----------
__device__ float  g_x [BCHW];          // state (16,32,265,265)
__device__ float  g_sp[BCHW];          // spectral-conv output (pre-norm)
__device__ float2 g_F1[BB*CC*NN*KK];   // width-DFT result
__device__ float2 g_Z [BB*CC*NN*KK];   // inverse-height result
__device__ float2 g_xs[BB*CC*SS*KK];   // modes, per input channel
__device__ float2 g_ys[BB*CC*SS*KK];   // modes, after channel mix
__device__ float  g_Wf[LL*CC*CC*SS*KK];// Wfull[l,i,o,si,k]
__device__ float2 g_twW[NN*KK];        // e^{-2pi i k w/265}  (cos, -sin)
__device__ float2 g_twH[NN*SS];        // e^{-2pi i (si-12) h/265}
__device__ float2 g_stat[BB*CC];       // (mean, rstd)

__device__ __forceinline__ float gelu_f(float x){
    return 0.5f*x*(1.0f+erff(x*0.70710678118654752f));
}

// ---------------- Wfull construction (build_weights unrolled) ---------------
__global__ void k_wfull(const float* __restrict__ W_LC, const float* __restrict__ W_LR){
    int idx = blockIdx.x*blockDim.x + threadIdx.x;
    int total = LL*CC*CC*SS*KK;
    if (idx >= total) return;
    int c  = idx % KK;
    int xi = (idx/KK) % SS;
    int o  = (idx/(KK*SS)) % CC;
    int i  = (idx/(KK*SS*CC)) % CC;
    int l  = idx/(KK*SS*CC*CC);
    int lcBase = ((l*CC+i)*CC+o)*KK;          // W_LC[l,i,o,*]
    int lrBase = (((l*CC+i)*CC+o)*12)*12;     // W_LR[l,i,o,*,*]
    float v;
    if (xi < 13){
        if (c == 0){
            v = W_LC[lcBase + (12 - xi)];
        } else {
            int cc = 12 - xi;                 // column inside W_LRc, row r=c-1
            if (cc == 0) v = W_LC[lcBase + c];            // W_LRc[r,0]=W_LC[r+1]
            else         v = W_LR[lrBase + (c-1)*12 + (cc-1)];
        }
    } else {
        int r = xi - 13;                      // W_LRc row
        if (c == 0) v = W_LC[lcBase + (r+1)];
        else        v = W_LR[lrBase + r*12 + (c-1)];
    }
    g_Wf[idx] = v;
}

// ---------------- twiddle tables --------------------------------------------
__global__ void k_tw(){
    int idx = blockIdx.x*blockDim.x + threadIdx.x;
    if (idx < NN*KK){
        int w = idx / KK, k = idx % KK;
        int m = (w*k) % NN;
        float s, c;
        sincospif(2.0f*(float)m/(float)NN, &s, &c);
        g_twW[idx] = make_float2(c, -s);
    } else if (idx < NN*KK + NN*SS){
        int j = idx - NN*KK;
        int h = j / SS, si = j % SS;
        int s = si - 12;
        int m = ((s*h) % NN + NN) % NN;
        float sn, cs;
        sincospif(2.0f*(float)m/(float)NN, &sn, &cs);
        g_twH[j] = make_float2(cs, -sn);
    }
}

// ---------------- lifting + zero pad ----------------------------------------
__global__ void k_lift(const float* __restrict__ x, const float* __restrict__ pw,
                       const float* __restrict__ pb){
    int idx = blockIdx.x*blockDim.x + threadIdx.x;
    if (idx >= BCHW) return;
    int p = idx % HW;
    int c = (idx/HW) % CC;
    int b = idx/(HW*CC);
    int h = p / NN, w = p % NN;
    float v = 0.f;
    if (h < 256 && w < 256)
        v = fmaf(pw[c], x[b*65536 + h*256 + w], pb[c]);
    g_x[idx] = v;
}

// ---------------- per-(b,c) mean/rstd ---------------------------------------
__global__ void k_stats(int src_sel){
    int bc = blockIdx.x;
    const float* p = (src_sel ? g_sp : g_x) + (size_t)bc*HW;
    float s = 0.f, s2 = 0.f;
    for (int i = threadIdx.x; i < HW; i += blockDim.x){
        float v = p[i]; s += v; s2 = fmaf(v, v, s2);
    }
    __shared__ double sh[256], sh2[256];
    sh[threadIdx.x] = (double)s; sh2[threadIdx.x] = (double)s2;
    __syncthreads();
    for (int st = 128; st > 0; st >>= 1){
        if (threadIdx.x < st){ sh[threadIdx.x] += sh[threadIdx.x+st]; sh2[threadIdx.x] += sh2[threadIdx.x+st]; }
        __syncthreads();
    }
    if (threadIdx.x == 0){
        double m  = sh[0]/(double)HW;
        double va = sh2[0]/(double)HW - m*m;
        g_stat[bc] = make_float2((float)m, (float)(1.0/sqrt(va + 1e-5)));
    }
}

// ---------------- forward width DFT (normalization fused) -------------------
__global__ void k_fwdW(){
    int idx = blockIdx.x*blockDim.x + threadIdx.x;
    if (idx >= BB*CC*NN*KK) return;
    int k  = idx % KK;
    int h  = (idx/KK) % NN;
    int bc = idx/(KK*NN);
    float2 st = g_stat[bc];
    const float* row = g_x + (size_t)bc*HW + h*NN;
    float re = 0.f, im = 0.f;
    for (int w = 0; w < NN; ++w){
        float v = (row[w] - st.x) * st.y;
        float2 t = g_twW[w*KK + k];
        re = fmaf(v, t.x, re);
        im = fmaf(v, t.y, im);
    }
    g_F1[idx] = make_float2(re, im);
}

// ---------------- forward height DFT ----------------------------------------
__global__ void k_fwdH(){
    int idx = blockIdx.x*blockDim.x + threadIdx.x;
    if (idx >= BB*CC*SS*KK) return;
    int k  = idx % KK;
    int si = (idx/KK) % SS;
    int bc = idx/(KK*SS);
    const float2* F = g_F1 + (size_t)bc*NN*KK + k;
    float re = 0.f, im = 0.f;
    for (int h = 0; h < NN; ++h){
        float2 f = F[h*KK];
        float2 t = g_twH[h*SS + si];
        re += f.x*t.x - f.y*t.y;
        im += f.x*t.y + f.y*t.x;
    }
    g_xs[idx] = make_float2(re, im);
}

// ---------------- per-mode channel mix --------------------------------------
__global__ void k_mix(int l){
    int idx = blockIdx.x*blockDim.x + threadIdx.x;
    if (idx >= BB*CC*SS*KK) return;
    int k  = idx % KK;
    int si = (idx/KK) % SS;
    int o  = (idx/(KK*SS)) % CC;
    int b  = idx/(KK*SS*CC);
    float re = 0.f, im = 0.f;
    #pragma unroll 8
    for (int i = 0; i < CC; ++i){
        float w  = g_Wf[(((l*CC+i)*CC+o)*SS + si)*KK + k];
        float2 v = g_xs[((b*CC+i)*SS + si)*KK + k];
        re = fmaf(w, v.x, re);
        im = fmaf(w, v.y, im);
    }
    g_ys[((b*CC+o)*SS + si)*KK + k] = make_float2(re, im);
}

// ---------------- inverse height (conj twiddle) -----------------------------
__global__ void k_invH(){
    int idx = blockIdx.x*blockDim.x + threadIdx.x;
    if (idx >= BB*CC*NN*KK) return;
    int k  = idx % KK;
    int h  = (idx/KK) % NN;
    int bc = idx/(KK*NN);
    const float2* Y = g_ys + (size_t)bc*SS*KK + k;
    float re = 0.f, im = 0.f;
    #pragma unroll
    for (int si = 0; si < SS; ++si){
        float2 y = Y[si*KK];
        float2 t = g_twH[h*SS + si];           // e^{-i th}; want conj
        re += y.x*t.x + y.y*t.y;
        im += y.y*t.x - y.x*t.y;
    }
    g_Z[idx] = make_float2(re, im);
}

// ---------------- inverse width (real output, C2R) --------------------------
__global__ void k_invW(){
    int idx = blockIdx.x*blockDim.x + threadIdx.x;
    if (idx >= BCHW) return;
    int w  = idx % NN;
    int h  = (idx/NN) % NN;
    int bc = idx/HW;
    const float2* Z = g_Z + ((size_t)bc*NN + h)*KK;
    float acc = Z[0].x;
    #pragma unroll
    for (int k = 1; k < KK; ++k){
        float2 z = Z[k];
        float2 t = g_twW[w*KK + k];            // (cos, -sin); Re(z e^{+i}) = zx*t.x + zy*t.y
        acc += 2.f*(z.x*t.x + z.y*t.y);
    }
    g_sp[idx] = acc * (1.0f/(float)HW);
}

// ---------------- fused inorm2 + mlp1 + gelu + mlp2 + skip (+gelu) ----------
__global__ void __launch_bounds__(128) k_mlp(const float* __restrict__ m1, const float* __restrict__ b1,
                                             const float* __restrict__ m2, const float* __restrict__ b2,
                                             const float* __restrict__ ww, const float* __restrict__ wb,
                                             int act){
    __shared__ float s1[CC*CC], s2[CC*CC], sw[CC*CC], sb1[CC], sb2[CC], swb[CC];
    for (int i = threadIdx.x; i < CC*CC; i += blockDim.x){
        s1[i] = m1[i]; s2[i] = m2[i]; sw[i] = ww[i];
    }
    if (threadIdx.x < CC){
        sb1[threadIdx.x] = b1[threadIdx.x];
        sb2[threadIdx.x] = b2[threadIdx.x];
        swb[threadIdx.x] = wb[threadIdx.x];
    }
    __syncthreads();
    int pix = blockIdx.x*blockDim.x + threadIdx.x;
    if (pix >= BB*HW) return;
    int b = pix / HW;
    int p = pix % HW;
    size_t base = (size_t)b*CC*HW + p;

    float v0[CC], v1[CC];
    #pragma unroll
    for (int c = 0; c < CC; ++c){
        float2 st = g_stat[b*CC + c];
        v0[c] = g_x [base + (size_t)c*HW];
        v1[c] = (g_sp[base + (size_t)c*HW] - st.x) * st.y;
    }
    float t[CC];
    #pragma unroll
    for (int o = 0; o < CC; ++o){
        float a = sb1[o];
        #pragma unroll
        for (int c = 0; c < CC; ++c) a = fmaf(s1[o*CC+c], v1[c], a);
        t[o] = gelu_f(a);
    }
    #pragma unroll
    for (int o = 0; o < CC; ++o){
        float a = sb2[o] + swb[o];
        #pragma unroll
        for (int c = 0; c < CC; ++c) a = fmaf(s2[o*CC+c], t[c], fmaf(sw[o*CC+c], v0[c], a));
        if (act) a = gelu_f(a);
        g_x[base + (size_t)o*HW] = a;   // in-place safe: thread owns its pixel
    }
}

// ---------------- crop + q1 + gelu + q2 -------------------------------------
__global__ void __launch_bounds__(128) k_head(const float* __restrict__ q1w, const float* __restrict__ q1b,
                                              const float* __restrict__ q2w, const float* __restrict__ q2b,
                                              float* __restrict__ out){
    __shared__ float sq1[128*CC], sq1b[128], sq2[128];
    for (int i = threadIdx.x; i < 128*CC; i += blockDim.x) sq1[i] = q1w[i];
    if (threadIdx.x < 128){ sq1b[threadIdx.x] = q1b[threadIdx.x]; sq2[threadIdx.x] = q2w[threadIdx.x]; }
    __syncthreads();
    int idx = blockIdx.x*blockDim.x + threadIdx.x;
    if (idx >= BB*256*256) return;
    int b = idx / 65536;
    int p = idx % 65536;
    int h = p / 256, w = p % 256;
    size_t base = (size_t)b*CC*HW + h*NN + w;
    float v[CC];
    #pragma unroll
    for (int c = 0; c < CC; ++c) v[c] = g_x[base + (size_t)c*HW];
    float acc = q2b[0];
    for (int j = 0; j < 128; ++j){
        float a = sq1b[j];
        #pragma unroll
        for (int c = 0; c < CC; ++c) a = fmaf(sq1[j*CC+c], v[c], a);
        acc = fmaf(sq2[j], gelu_f(a), acc);
    }
    out[idx] = acc;
}

// ---------------- host orchestration ----------------------------------------
extern "C" void kernel_launch(void* const* d_in, const int* in_sizes, int n_in,
                              void* d_out, int out_size){
    const float* x     = (const float*)d_in[0];
    const float* p_w   = (const float*)d_in[1];
    const float* p_b   = (const float*)d_in[2];
    const float* W_LC  = (const float*)d_in[3];
    const float* W_LR  = (const float*)d_in[4];
    const float* m1w   = (const float*)d_in[5];
    const float* m1b   = (const float*)d_in[6];
    const float* m2w   = (const float*)d_in[7];
    const float* m2b   = (const float*)d_in[8];
    const float* w_w   = (const float*)d_in[9];
    const float* w_b   = (const float*)d_in[10];
    const float* q1w   = (const float*)d_in[11];
    const float* q1b   = (const float*)d_in[12];
    const float* q2w   = (const float*)d_in[13];
    const float* q2b   = (const float*)d_in[14];
    float* out = (float*)d_out;

    const int wfN = LL*CC*CC*SS*KK;
    k_wfull<<<(wfN+255)/256, 256>>>(W_LC, W_LR);
    k_tw<<<(NN*KK + NN*SS + 255)/256, 256>>>();
    k_lift<<<(BCHW+255)/256, 256>>>(x, p_w, p_b);

    const int nF1 = BB*CC*NN*KK;
    const int nXs = BB*CC*SS*KK;
    for (int l = 0; l < LL; ++l){
        k_stats<<<BB*CC, 256>>>(0);
        k_fwdW<<<(nF1+255)/256, 256>>>();
        k_fwdH<<<(nXs+255)/256, 256>>>();
        k_mix <<<(nXs+255)/256, 256>>>(l);
        k_invH<<<(nF1+255)/256, 256>>>();
        k_invW<<<(BCHW+255)/256, 256>>>();
        k_stats<<<BB*CC, 256>>>(1);
        k_mlp<<<(BB*HW + 127)/128, 128>>>(m1w + l*CC*CC, m1b + l*CC,
                                          m2w + l*CC*CC, m2b + l*CC,
                                          w_w + l*CC*CC, w_b + l*CC,
                                          (l < LL-1) ? 1 : 0);
    }
    k_head<<<(BB*256*256 + 127)/128, 128>>>(q1w, q1b, q2w, q2b, out);
}

// round 3
// speedup vs baseline: 1.2945x; 1.2945x over previous
#include <cuda_runtime.h>
#include <math.h>

#define BB 16
#define CC 32
#define NN 265
#define HW (NN*NN)          // 70225
#define KK 13               // width modes
#define SS 25               // height modes (s = si-12)
#define LL 4
#define BCHW (BB*CC*HW)

// ---------------- device scratch ----------------
__device__ float  g_x [BCHW];          // state
__device__ float  g_sp[BCHW];          // spectral output
__device__ float2 g_F1[BB*CC*NN*KK];   // width-DFT result
__device__ float2 g_Z [BB*CC*NN*KK];   // inverse-height result
__device__ float2 g_xs[BB*CC*SS*KK];
__device__ float2 g_ys[BB*CC*SS*KK];
__device__ float  g_Wf[LL*CC*CC*SS*KK];
__device__ float2 g_twH[NN*SS];        // e^{-2pi i (si-12) h / N}
__device__ float2 g_stepK[KK];         // e^{-2pi i k / N}
__device__ float2 g_twW1[NN];          // e^{+2pi i w / N}
__device__ float2 g_stat[BB*CC];       // (mean, rstd)
__device__ double g_accA[BB*CC*2];     // x-stat partials
__device__ double g_accB[BB*CC*2];     // sp-stat partials

__device__ __forceinline__ float gelu_f(float x){
    return 0.5f*x*(1.0f+erff(x*0.70710678118654752f));
}

// block reduce (s, s2) -> 2 double atomics
__device__ __forceinline__ void blk_acc(float s, float s2, double* acc){
    #pragma unroll
    for (int off = 16; off > 0; off >>= 1){
        s  += __shfl_down_sync(0xffffffffu, s,  off);
        s2 += __shfl_down_sync(0xffffffffu, s2, off);
    }
    __shared__ float ws[8], ws2[8];
    int lane = threadIdx.x & 31, wid = threadIdx.x >> 5;
    if (lane == 0){ ws[wid] = s; ws2[wid] = s2; }
    __syncthreads();
    if (threadIdx.x == 0){
        float t = 0.f, t2 = 0.f;
        int nw = (blockDim.x + 31) >> 5;
        for (int w = 0; w < nw; ++w){ t += ws[w]; t2 += ws2[w]; }
        atomicAdd(acc,   (double)t);
        atomicAdd(acc+1, (double)t2);
    }
}

__global__ void k_zero(){
    int i = threadIdx.x;
    if (i < BB*CC){ g_accA[2*i]=0.0; g_accA[2*i+1]=0.0; g_accB[2*i]=0.0; g_accB[2*i+1]=0.0; }
}

// ---------------- Wfull ----------------
__global__ void k_wfull(const float* __restrict__ W_LC, const float* __restrict__ W_LR){
    int idx = blockIdx.x*blockDim.x + threadIdx.x;
    int total = LL*CC*CC*SS*KK;
    if (idx >= total) return;
    int c  = idx % KK;
    int xi = (idx/KK) % SS;
    int o  = (idx/(KK*SS)) % CC;
    int i  = (idx/(KK*SS*CC)) % CC;
    int l  = idx/(KK*SS*CC*CC);
    int lcBase = ((l*CC+i)*CC+o)*KK;
    int lrBase = (((l*CC+i)*CC+o)*12)*12;
    float v;
    if (xi < 13){
        if (c == 0){
            v = W_LC[lcBase + (12 - xi)];
        } else {
            int cc = 12 - xi;
            if (cc == 0) v = W_LC[lcBase + c];
            else         v = W_LR[lrBase + (c-1)*12 + (cc-1)];
        }
    } else {
        int r = xi - 13;
        if (c == 0) v = W_LC[lcBase + (r+1)];
        else        v = W_LR[lrBase + r*12 + (c-1)];
    }
    g_Wf[idx] = v;
}

// ---------------- twiddle tables ----------------
__global__ void k_tw(){
    int idx = blockIdx.x*blockDim.x + threadIdx.x;
    if (idx < NN*SS){
        int h = idx / SS, si = idx % SS;
        int s = si - 12;
        int m = ((s*h) % NN + NN) % NN;
        float sn, cs;
        sincospif(2.0f*(float)m/(float)NN, &sn, &cs);
        g_twH[idx] = make_float2(cs, -sn);
    } else if (idx < NN*SS + KK){
        int k = idx - NN*SS;
        float sn, cs;
        sincospif(2.0f*(float)k/(float)NN, &sn, &cs);
        g_stepK[k] = make_float2(cs, -sn);
    } else if (idx < NN*SS + KK + NN){
        int w = idx - NN*SS - KK;
        float sn, cs;
        sincospif(2.0f*(float)w/(float)NN, &sn, &cs);
        g_twW1[w] = make_float2(cs, sn);
    }
}

// ---------------- lifting + pad + x-stat accumulation ----------------
__global__ void k_lift(const float* __restrict__ x, const float* __restrict__ pw,
                       const float* __restrict__ pb){
    int bc = blockIdx.y;
    int c = bc % CC, b = bc / CC;
    int p = blockIdx.x*blockDim.x + threadIdx.x;
    float v = 0.f;
    if (p < HW){
        int h = p / NN, w = p % NN;
        if (h < 256 && w < 256)
            v = fmaf(pw[c], x[b*65536 + h*256 + w], pb[c]);
        g_x[(size_t)bc*HW + p] = v;
    }
    blk_acc(v, v*v, g_accA + 2*bc);
}

// ---------------- mid-network x stats (chunked partials) ----------------
__global__ void k_stats2(){
    int bc = blockIdx.y;
    const float* p = g_x + (size_t)bc*HW;
    int start = blockIdx.x * 8779;
    int end   = min(start + 8779, HW);
    float s = 0.f, s2 = 0.f;
    for (int i = start + threadIdx.x; i < end; i += blockDim.x){
        float v = p[i]; s += v; s2 = fmaf(v, v, s2);
    }
    blk_acc(s, s2, g_accA + 2*bc);
}

// ---------------- finalize stats, zero accumulators ----------------
__global__ void k_fin(int which){
    int bc = threadIdx.x;
    if (bc >= BB*CC) return;
    double* acc = (which ? g_accB : g_accA) + 2*bc;
    double m  = acc[0] / (double)HW;
    double va = acc[1] / (double)HW - m*m;
    g_stat[bc] = make_float2((float)m, (float)(1.0/sqrt(va + 1e-5)));
    acc[0] = 0.0; acc[1] = 0.0;
}

// ---------------- forward width DFT: shared rows + twiddle recurrence ------
#define TH 19
__global__ void __launch_bounds__(256) k_fwdW(){
    __shared__ float srow[TH*NN];
    int bc = blockIdx.y;
    int h0 = blockIdx.x * TH;
    int rows = min(TH, NN - h0);
    float2 st = g_stat[bc];
    const float* src = g_x + (size_t)bc*HW + (size_t)h0*NN;
    for (int i = threadIdx.x; i < rows*NN; i += 256)
        srow[i] = (src[i] - st.x) * st.y;
    __syncthreads();
    int tid = threadIdx.x;
    if (tid >= rows*KK) return;
    int hl = tid / KK, k = tid % KK;
    float2 stp = g_stepK[k];
    const float* r = srow + hl*NN;
    float c = 1.f, s = 0.f, re = 0.f, im = 0.f;
    #pragma unroll 5
    for (int w = 0; w < NN; ++w){
        float v = r[w];
        re = fmaf(v, c, re);
        im = fmaf(v, s, im);
        float cn = c*stp.x - s*stp.y;
        s = fmaf(c, stp.y, s*stp.x);
        c = cn;
    }
    g_F1[((size_t)bc*NN + (h0+hl))*KK + k] = make_float2(re, im);
}

// ---------------- forward height DFT ----------------
__global__ void k_fwdH(){
    int idx = blockIdx.x*blockDim.x + threadIdx.x;
    if (idx >= BB*CC*SS*KK) return;
    int k  = idx % KK;
    int si = (idx/KK) % SS;
    int bc = idx/(KK*SS);
    const float2* F = g_F1 + (size_t)bc*NN*KK + k;
    float re = 0.f, im = 0.f;
    for (int h = 0; h < NN; ++h){
        float2 f = F[h*KK];
        float2 t = g_twH[h*SS + si];
        re += f.x*t.x - f.y*t.y;
        im += f.x*t.y + f.y*t.x;
    }
    g_xs[idx] = make_float2(re, im);
}

// ---------------- per-mode channel mix ----------------
__global__ void k_mix(int l){
    int idx = blockIdx.x*blockDim.x + threadIdx.x;
    if (idx >= BB*CC*SS*KK) return;
    int k  = idx % KK;
    int si = (idx/KK) % SS;
    int o  = (idx/(KK*SS)) % CC;
    int b  = idx/(KK*SS*CC);
    float re = 0.f, im = 0.f;
    #pragma unroll 8
    for (int i = 0; i < CC; ++i){
        float w  = g_Wf[(((l*CC+i)*CC+o)*SS + si)*KK + k];
        float2 v = g_xs[((b*CC+i)*SS + si)*KK + k];
        re = fmaf(w, v.x, re);
        im = fmaf(w, v.y, im);
    }
    g_ys[((b*CC+o)*SS + si)*KK + k] = make_float2(re, im);
}

// ---------------- inverse height ----------------
__global__ void k_invH(){
    int idx = blockIdx.x*blockDim.x + threadIdx.x;
    if (idx >= BB*CC*NN*KK) return;
    int k  = idx % KK;
    int h  = (idx/KK) % NN;
    int bc = idx/(KK*NN);
    const float2* Y = g_ys + (size_t)bc*SS*KK + k;
    float re = 0.f, im = 0.f;
    #pragma unroll
    for (int si = 0; si < SS; ++si){
        float2 y = Y[si*KK];
        float2 t = g_twH[h*SS + si];          // conj applied below
        re += y.x*t.x + y.y*t.y;
        im += y.y*t.x - y.x*t.y;
    }
    g_Z[idx] = make_float2(re, im);
}

// ---------------- inverse width (C2R) + sp-stat accumulation ----------------
__global__ void __launch_bounds__(256) k_invW(){
    int bc = blockIdx.y;
    int p = blockIdx.x*blockDim.x + threadIdx.x;
    float val = 0.f;
    if (p < HW){
        int h = p / NN, w = p % NN;
        const float2* Zr = g_Z + ((size_t)bc*NN + h)*KK;
        float2 stp = g_twW1[w];               // e^{+2pi i w/N}
        float acc = Zr[0].x;
        float tc = stp.x, ts = stp.y;
        #pragma unroll
        for (int k = 1; k < KK; ++k){
            float2 z = Zr[k];
            acc += 2.f*(z.x*tc - z.y*ts);
            float tn = tc*stp.x - ts*stp.y;
            ts = fmaf(tc, stp.y, ts*stp.x);
            tc = tn;
        }
        val = acc * (1.0f/(float)HW);
        g_sp[(size_t)bc*HW + p] = val;
    }
    blk_acc(val, val*val, g_accB + 2*bc);
}

// ---------------- fused inorm + mlp1 + gelu + mlp2 + skip (+gelu) ----------
__global__ void __launch_bounds__(128) k_mlp(const float* __restrict__ m1, const float* __restrict__ b1,
                                             const float* __restrict__ m2, const float* __restrict__ b2,
                                             const float* __restrict__ ww, const float* __restrict__ wb,
                                             int act){
    __shared__ float s1[CC*CC], s2[CC*CC], sw[CC*CC], sb1[CC], sb2[CC], swb[CC];
    for (int i = threadIdx.x; i < CC*CC; i += blockDim.x){
        s1[i] = m1[i]; s2[i] = m2[i]; sw[i] = ww[i];
    }
    if (threadIdx.x < CC){
        sb1[threadIdx.x] = b1[threadIdx.x];
        sb2[threadIdx.x] = b2[threadIdx.x];
        swb[threadIdx.x] = wb[threadIdx.x];
    }
    __syncthreads();
    int pix = blockIdx.x*blockDim.x + threadIdx.x;
    if (pix >= BB*HW) return;
    int b = pix / HW;
    int p = pix % HW;
    size_t base = (size_t)b*CC*HW + p;

    float v0[CC], v1[CC];
    #pragma unroll
    for (int c = 0; c < CC; ++c){
        float2 st = g_stat[b*CC + c];
        v0[c] = g_x [base + (size_t)c*HW];
        v1[c] = (g_sp[base + (size_t)c*HW] - st.x) * st.y;
    }
    float t[CC];
    #pragma unroll
    for (int o = 0; o < CC; ++o){
        float a = sb1[o];
        #pragma unroll
        for (int c = 0; c < CC; ++c) a = fmaf(s1[o*CC+c], v1[c], a);
        t[o] = gelu_f(a);
    }
    #pragma unroll
    for (int o = 0; o < CC; ++o){
        float a = sb2[o] + swb[o];
        #pragma unroll
        for (int c = 0; c < CC; ++c) a = fmaf(s2[o*CC+c], t[c], fmaf(sw[o*CC+c], v0[c], a));
        if (act) a = gelu_f(a);
        g_x[base + (size_t)o*HW] = a;
    }
}

// ---------------- crop + q1 + gelu + q2 ----------------
__global__ void __launch_bounds__(128) k_head(const float* __restrict__ q1w, const float* __restrict__ q1b,
                                              const float* __restrict__ q2w, const float* __restrict__ q2b,
                                              float* __restrict__ out){
    __shared__ float sq1[128*CC], sq1b[128], sq2[128];
    for (int i = threadIdx.x; i < 128*CC; i += blockDim.x) sq1[i] = q1w[i];
    if (threadIdx.x < 128){ sq1b[threadIdx.x] = q1b[threadIdx.x]; sq2[threadIdx.x] = q2w[threadIdx.x]; }
    __syncthreads();
    int idx = blockIdx.x*blockDim.x + threadIdx.x;
    if (idx >= BB*256*256) return;
    int b = idx / 65536;
    int p = idx % 65536;
    int h = p / 256, w = p % 256;
    size_t base = (size_t)b*CC*HW + (size_t)h*NN + w;
    float v[CC];
    #pragma unroll
    for (int c = 0; c < CC; ++c) v[c] = g_x[base + (size_t)c*HW];
    float acc = q2b[0];
    for (int j = 0; j < 128; ++j){
        float a = sq1b[j];
        #pragma unroll
        for (int c = 0; c < CC; ++c) a = fmaf(sq1[j*CC+c], v[c], a);
        acc = fmaf(sq2[j], gelu_f(a), acc);
    }
    out[idx] = acc;
}

// ---------------- host orchestration ----------------
extern "C" void kernel_launch(void* const* d_in, const int* in_sizes, int n_in,
                              void* d_out, int out_size){
    const float* x     = (const float*)d_in[0];
    const float* p_w   = (const float*)d_in[1];
    const float* p_b   = (const float*)d_in[2];
    const float* W_LC  = (const float*)d_in[3];
    const float* W_LR  = (const float*)d_in[4];
    const float* m1w   = (const float*)d_in[5];
    const float* m1b   = (const float*)d_in[6];
    const float* m2w   = (const float*)d_in[7];
    const float* m2b   = (const float*)d_in[8];
    const float* w_w   = (const float*)d_in[9];
    const float* w_b   = (const float*)d_in[10];
    const float* q1w   = (const float*)d_in[11];
    const float* q1b   = (const float*)d_in[12];
    const float* q2w   = (const float*)d_in[13];
    const float* q2b   = (const float*)d_in[14];
    float* out = (float*)d_out;

    k_zero<<<1, 512>>>();
    const int wfN = LL*CC*CC*SS*KK;
    k_wfull<<<(wfN+255)/256, 256>>>(W_LC, W_LR);
    k_tw<<<(NN*SS + KK + NN + 255)/256, 256>>>();

    dim3 gPix((HW + 255)/256, BB*CC);
    k_lift<<<gPix, 256>>>(x, p_w, p_b);

    const int nF1 = BB*CC*NN*KK;
    const int nXs = BB*CC*SS*KK;
    for (int l = 0; l < LL; ++l){
        if (l > 0) k_stats2<<<dim3(8, BB*CC), 256>>>();
        k_fin<<<1, 512>>>(0);
        k_fwdW<<<dim3((NN + TH - 1)/TH, BB*CC), 256>>>();
        k_fwdH<<<(nXs+255)/256, 256>>>();
        k_mix <<<(nXs+255)/256, 256>>>(l);
        k_invH<<<(nF1+255)/256, 256>>>();
        k_invW<<<gPix, 256>>>();
        k_fin<<<1, 512>>>(1);
        k_mlp<<<(BB*HW + 127)/128, 128>>>(m1w + l*CC*CC, m1b + l*CC,
                                          m2w + l*CC*CC, m2b + l*CC,
                                          w_w + l*CC*CC, w_b + l*CC,
                                          (l < LL-1) ? 1 : 0);
    }
    k_head<<<(BB*256*256 + 127)/128, 128>>>(q1w, q1b, q2w, q2b, out);
}